// round 15
// baseline (speedup 1.0000x reference)
#include <cuda_runtime.h>
#include <cuda_fp16.h>
#include <cstdint>

// ============================================================================
// out = gelu( x @ ((fc1_w^T @ fc2_w^T + b) * mask) )   — fp32 in/out
// fp16 mma.sync.m16n8k16, f32 accumulate.
// R15: heterogeneous co-residency via streams —
//   side stream: cvt_x in 64-thread/low-reg CTAs (fits in the RF slack that
//                GEMM1's R9 shape leaves: 2x128x240 = 61440 of 65536 regs)
//   main stream: prep_fused -> GEMM1 (R9 shape: 128thr, 64x64 warp tile)
//                -> fixup;  join -> GEMM2 (R7 body, untouched).
// ============================================================================

__device__ __half g_xh[49152 * 1024];
__device__ __half g_fc1T[1024 * 4096];
__device__ __half g_fc2h[1024 * 4096];
__device__ float  g_part[4 * 1024 * 1024];
__device__ __half g_attnT[1024 * 1024];

// ---------------- helpers ---------------------------------------------------
__device__ __forceinline__ uint32_t smem_u32(const void* p) {
    uint32_t a;
    asm("{ .reg .u64 t; cvta.to.shared.u64 t, %1; cvt.u32.u64 %0, t; }" : "=r"(a) : "l"(p));
    return a;
}
#define CP_ASYNC16(sdst, gsrc) \
    asm volatile("cp.async.cg.shared.global [%0], [%1], 16;" :: "r"(sdst), "l"(gsrc) : "memory")
#define CP_COMMIT() asm volatile("cp.async.commit_group;" ::: "memory")
#define CP_WAIT1()  asm volatile("cp.async.wait_group 1;" ::: "memory")
#define CP_WAIT0()  asm volatile("cp.async.wait_group 0;" ::: "memory")
#define SWZ128(off) ((off) ^ (((off) >> 3) & 0x70))

__device__ __forceinline__ void ldsm_x4(uint32_t* r, uint32_t addr) {
    asm volatile("ldmatrix.sync.aligned.m8n8.x4.shared.b16 {%0,%1,%2,%3}, [%4];"
                 : "=r"(r[0]), "=r"(r[1]), "=r"(r[2]), "=r"(r[3]) : "r"(addr));
}
// fp16 MMA, fp32 accumulate: C[16x8] += A[16x16] * B[16x8]
__device__ __forceinline__ void mma_f16(float c[4], const uint32_t a[4], const uint32_t* b) {
    asm volatile(
        "mma.sync.aligned.m16n8k16.row.col.f32.f16.f16.f32 "
        "{%0,%1,%2,%3}, {%4,%5,%6,%7}, {%8,%9}, {%0,%1,%2,%3};"
        : "+f"(c[0]), "+f"(c[1]), "+f"(c[2]), "+f"(c[3])
        : "r"(a[0]), "r"(a[1]), "r"(a[2]), "r"(a[3]), "r"(b[0]), "r"(b[1]));
}
__device__ __forceinline__ float gelu_exact(float u) {
    return 0.5f * u * (1.0f + erff(u * 0.7071067811865476f));
}

constexpr int STAGES = 3;
constexpr int TBYTES = 128 * 128;   // 128 rows x 64 halfs (16KB)

// ---------------------------------------------------------------------------
// GEMM1 (R9 shape): 128 threads, 4 warps @ 64x64 warp tile, CTA 128x128.
// ~240 regs/thread -> 2 CTAs/SM leaves 4K regs for co-resident cvt CTAs.
// 3-stage cp.async + wait_group(1). splitK via blockIdx.z.
// ---------------------------------------------------------------------------
__global__ __launch_bounds__(128, 2) void g1_kernel(
    const __half* __restrict__ A, const __half* __restrict__ B, float* __restrict__ C,
    int M, int N, int lda, int ldb, int kSplit)
{
    extern __shared__ __align__(1024) char smem[];
    const uint32_t sb = smem_u32(smem);
    const int tid  = threadIdx.x;
    const int lane = tid & 31;
    const int wid  = tid >> 5;           // 0..3
    const int wm   = (wid & 1) * 64;
    const int wn   = (wid >> 1) * 64;
    const size_t bm = (size_t)blockIdx.y * 128;
    const size_t bn = (size_t)blockIdx.x * 128;

    const __half* Ab = A + (size_t)blockIdx.z * kSplit;
    const __half* Bb = B + (size_t)blockIdx.z * kSplit;

    const int nk = kSplit / 64;
    const int lr = tid >> 3;             // 0..15
    const int lc = tid & 7;
    auto issue = [&](int chunk) {
        const int buf = chunk % STAGES;
        const uint32_t aBase = sb + buf * TBYTES;
        const uint32_t bBase = sb + STAGES * TBYTES + buf * TBYTES;
        const __half* ga = Ab + (bm + lr) * (size_t)lda + chunk * 64 + lc * 8;
        const __half* gb = Bb + (bn + lr) * (size_t)ldb + chunk * 64 + lc * 8;
#pragma unroll
        for (int j = 0; j < 8; j++) {
            CP_ASYNC16(aBase + SWZ128((lr + j * 16) * 128 + lc * 16), ga + (size_t)(j * 16) * lda);
            CP_ASYNC16(bBase + SWZ128((lr + j * 16) * 128 + lc * 16), gb + (size_t)(j * 16) * ldb);
        }
        CP_COMMIT();
    };

    float c[4][8][4];
#pragma unroll
    for (int im = 0; im < 4; im++)
#pragma unroll
        for (int in = 0; in < 8; in++)
#pragma unroll
            for (int q = 0; q < 4; q++) c[im][in][q] = 0.0f;

    issue(0);
    issue(1);

    const int aRow = lane & 15;
    const int aKo  = ((lane >> 4) & 1) * 16;
    const int bRow = (lane & 7) + ((lane >> 4) << 3);
    const int bKo  = ((lane >> 3) & 1) * 16;

    for (int i = 0; i < nk; i++) {
        if (i + 1 < nk) { CP_WAIT1(); } else { CP_WAIT0(); }
        __syncthreads();
        if (i + 2 < nk) issue(i + 2);

        const uint32_t aS = sb + (i % STAGES) * TBYTES;
        const uint32_t bS = sb + STAGES * TBYTES + (i % STAGES) * TBYTES;
#pragma unroll
        for (int ks = 0; ks < 4; ks++) {
            uint32_t af[4][4];
#pragma unroll
            for (int im = 0; im < 4; im++)
                ldsm_x4(af[im], aS + SWZ128((wm + im * 16 + aRow) * 128 + ks * 32 + aKo));
#pragma unroll
            for (int nb = 0; nb < 4; nb++) {
                uint32_t bf[4];
                ldsm_x4(bf, bS + SWZ128((wn + nb * 16 + bRow) * 128 + ks * 32 + bKo));
#pragma unroll
                for (int im = 0; im < 4; im++) {
                    mma_f16(c[im][nb * 2 + 0], af[im], &bf[0]);
                    mma_f16(c[im][nb * 2 + 1], af[im], &bf[2]);
                }
            }
        }
    }

    float* Cb = C + (size_t)blockIdx.z * ((size_t)M * N);
    const int g  = lane >> 2;
    const int tg = lane & 3;
#pragma unroll
    for (int im = 0; im < 4; im++) {
#pragma unroll
        for (int in = 0; in < 8; in++) {
            const size_t r0 = bm + wm + im * 16 + g;
            const size_t r1 = r0 + 8;
            const size_t cc = bn + wn + in * 8 + tg * 2;
            *reinterpret_cast<float2*>(Cb + r0 * N + cc) = make_float2(c[im][in][0], c[im][in][1]);
            *reinterpret_cast<float2*>(Cb + r1 * N + cc) = make_float2(c[im][in][2], c[im][in][3]);
        }
    }
}

// ---------------------------------------------------------------------------
// GEMM2 (R7 body, untouched): CTA 128x128, 256 thr, warp tile 32x64,
// 3-stage cp.async + wait_group(1), fragment double-buffering, gelu epilogue.
// ---------------------------------------------------------------------------
__global__ __launch_bounds__(256, 2) void hgemm2(
    const __half* __restrict__ A, const __half* __restrict__ B, float* __restrict__ C,
    int M, int N, int K)
{
    extern __shared__ __align__(1024) char smem[];
    const uint32_t sb = smem_u32(smem);
    const int tid  = threadIdx.x;
    const int lane = tid & 31;
    const int wid  = tid >> 5;
    const int wm   = (wid & 3) * 32;
    const int wn   = (wid >> 2) * 64;
    const size_t bm = (size_t)blockIdx.y * 128;
    const size_t bn = (size_t)blockIdx.x * 128;

    const int nk = K / 64;
    const int lr = tid >> 3;
    const int lc = tid & 7;
    auto issue = [&](int chunk) {
        const int buf = chunk % STAGES;
        const uint32_t aBase = sb + buf * TBYTES;
        const uint32_t bBase = sb + STAGES * TBYTES + buf * TBYTES;
        const __half* ga = A + (bm + lr) * (size_t)K + chunk * 64 + lc * 8;
        const __half* gb = B + (bn + lr) * (size_t)K + chunk * 64 + lc * 8;
#pragma unroll
        for (int j = 0; j < 4; j++) {
            CP_ASYNC16(aBase + SWZ128((lr + j * 32) * 128 + lc * 16), ga + (size_t)(j * 32) * K);
            CP_ASYNC16(bBase + SWZ128((lr + j * 32) * 128 + lc * 16), gb + (size_t)(j * 32) * K);
        }
        CP_COMMIT();
    };

    float c[2][8][4];
#pragma unroll
    for (int im = 0; im < 2; im++)
#pragma unroll
        for (int in = 0; in < 8; in++)
#pragma unroll
            for (int q = 0; q < 4; q++) c[im][in][q] = 0.0f;

    issue(0);
    issue(1);

    const int aRow = lane & 15;
    const int aKo  = ((lane >> 4) & 1) * 16;
    const int bRow = (lane & 7) + ((lane >> 4) << 3);
    const int bKo  = ((lane >> 3) & 1) * 16;

    auto loadA = [&](uint32_t (*f)[4], uint32_t aS, int ks) {
#pragma unroll
        for (int im = 0; im < 2; im++)
            ldsm_x4(f[im], aS + SWZ128((wm + im * 16 + aRow) * 128 + ks * 32 + aKo));
    };
    auto loadB = [&](uint32_t (*f)[4], uint32_t bS, int ks) {
#pragma unroll
        for (int nb = 0; nb < 4; nb++)
            ldsm_x4(f[nb], bS + SWZ128((wn + nb * 16 + bRow) * 128 + ks * 32 + bKo));
    };

    for (int i = 0; i < nk; i++) {
        if (i + 1 < nk) { CP_WAIT1(); } else { CP_WAIT0(); }
        __syncthreads();
        if (i + 2 < nk) issue(i + 2);

        const uint32_t aS = sb + (i % STAGES) * TBYTES;
        const uint32_t bS = sb + STAGES * TBYTES + (i % STAGES) * TBYTES;

        uint32_t af[2][2][4];
        uint32_t bf[2][4][4];
        loadA(af[0], aS, 0);
        loadB(bf[0], bS, 0);
#pragma unroll
        for (int ks = 0; ks < 4; ks++) {
            const int cur = ks & 1, nxt = cur ^ 1;
            if (ks < 3) {
                loadA(af[nxt], aS, ks + 1);
                loadB(bf[nxt], bS, ks + 1);
            }
#pragma unroll
            for (int im = 0; im < 2; im++)
#pragma unroll
                for (int nb = 0; nb < 4; nb++) {
                    mma_f16(c[im][nb * 2 + 0], af[cur][im], &bf[cur][nb][0]);
                    mma_f16(c[im][nb * 2 + 1], af[cur][im], &bf[cur][nb][2]);
                }
        }
    }

    const int g  = lane >> 2;
    const int tg = lane & 3;
#pragma unroll
    for (int im = 0; im < 2; im++) {
#pragma unroll
        for (int in = 0; in < 8; in++) {
            const size_t r0 = bm + wm + im * 16 + g;
            const size_t r1 = r0 + 8;
            const size_t cc = bn + wn + in * 8 + tg * 2;
            float v0 = gelu_exact(c[im][in][0]);
            float v1 = gelu_exact(c[im][in][1]);
            float v2 = gelu_exact(c[im][in][2]);
            float v3 = gelu_exact(c[im][in][3]);
            *reinterpret_cast<float2*>(C + r0 * N + cc) = make_float2(v0, v1);
            *reinterpret_cast<float2*>(C + r1 * N + cc) = make_float2(v2, v3);
        }
    }
}

// --- cvt_x: 64-thread, low-reg CTAs -> co-reside with g1_kernel's RF slack ---
__global__ __launch_bounds__(64) void cvt64(const float4* __restrict__ in,
                                            __half2* __restrict__ out, int n4)
{
    int i = blockIdx.x * 64 + threadIdx.x;
    const int stride = gridDim.x * 64;
    for (; i < n4; i += stride) {
        float4 v = in[i];
        out[i * 2 + 0] = __floats2half2_rn(v.x, v.y);
        out[i * 2 + 1] = __floats2half2_rn(v.z, v.w);
    }
}

// ---------------------------------------------------------------------------
// Fused prep: blocks [0,1024) = cvt_fc2, blocks [1024,5120) = transpose+cvt fc1.
// ---------------------------------------------------------------------------
__global__ __launch_bounds__(256) void prep_fused(
    const float4* __restrict__ fc2, __half2* __restrict__ fc2h,
    const float* __restrict__ fc1, __half* __restrict__ fc1T)
{
    const int b = blockIdx.x;
    if (b < 1024) {
        const int base = b * 1024 + threadIdx.x;
#pragma unroll
        for (int k = 0; k < 4; k++) {
            const int i = base + k * 256;
            float4 v = fc2[i];
            fc2h[i * 2 + 0] = __floats2half2_rn(v.x, v.y);
            fc2h[i * 2 + 1] = __floats2half2_rn(v.z, v.w);
        }
    } else {
        __shared__ float t[32][33];
        const int i  = b - 1024;
        const int bx = (i & 31) * 32;
        const int by = (i >> 5) * 32;
        const int x = threadIdx.x & 31;
        const int y = threadIdx.x >> 5;
#pragma unroll
        for (int j = 0; j < 32; j += 8)
            t[y + j][x] = fc1[(size_t)(by + y + j) * 1024 + bx + x];
        __syncthreads();
#pragma unroll
        for (int j = 0; j < 32; j += 8)
            fc1T[(size_t)(bx + y + j) * 4096 + by + x] = __float2half_rn(t[x][y + j]);
    }
}

// fixup: attnT[t][s] = half( (sum_sk part[sk][s][t] + bias[t]) * mask[s][t] )
__global__ void fixup_k(const float* __restrict__ part, const float* __restrict__ bias,
                        const float* __restrict__ mask, __half* __restrict__ attnT)
{
    __shared__ float t[32][33];
    int bt = blockIdx.x * 32;
    int bs = blockIdx.y * 32;
    int x = threadIdx.x, y = threadIdx.y;
#pragma unroll
    for (int j = 0; j < 32; j += 8) {
        int s = bs + y + j, tc = bt + x;
        size_t idx = (size_t)s * 1024 + tc;
        float v = part[idx] + part[idx + 1048576] + part[idx + 2097152] + part[idx + 3145728];
        v = (v + bias[tc]) * mask[idx];
        t[y + j][x] = v;
    }
    __syncthreads();
#pragma unroll
    for (int j = 0; j < 32; j += 8)
        attnT[(size_t)(bt + y + j) * 1024 + bs + x] = __float2half_rn(t[x][y + j]);
}

// ---------------------------------------------------------------------------
extern "C" void kernel_launch(void* const* d_in, const int* in_sizes, int n_in,
                              void* d_out, int out_size)
{
    const float* x    = (const float*)d_in[0];
    const float* fc1  = (const float*)d_in[1];
    const float* fc2  = (const float*)d_in[2];
    const float* bias = (const float*)d_in[3];
    const float* mask = (const float*)d_in[4];
    float* out = (float*)d_out;

    __half *xh, *fc1T, *fc2h, *attnT;
    float* part;
    cudaGetSymbolAddress((void**)&xh, g_xh);
    cudaGetSymbolAddress((void**)&fc1T, g_fc1T);
    cudaGetSymbolAddress((void**)&fc2h, g_fc2h);
    cudaGetSymbolAddress((void**)&part, g_part);
    cudaGetSymbolAddress((void**)&attnT, g_attnT);

    constexpr int SMEM = 2 * STAGES * TBYTES;   // 98304
    cudaFuncSetAttribute(g1_kernel, cudaFuncAttributeMaxDynamicSharedMemorySize, SMEM);
    cudaFuncSetAttribute(hgemm2, cudaFuncAttributeMaxDynamicSharedMemorySize, SMEM);

    // ---- fork: cvt_x (tiny CTAs) on side stream, runs under the whole chain ----
    cudaStream_t side;
    cudaEvent_t evFork, evJoin;
    cudaStreamCreateWithFlags(&side, cudaStreamNonBlocking);
    cudaEventCreateWithFlags(&evFork, cudaEventDisableTiming);
    cudaEventCreateWithFlags(&evJoin, cudaEventDisableTiming);

    cudaEventRecord(evFork, 0);
    cudaStreamWaitEvent(side, evFork, 0);
    cvt64<<<8192, 64, 0, side>>>((const float4*)x, (__half2*)xh, 49152 * 1024 / 4);
    cudaEventRecord(evJoin, side);

    // ---- main chain ----
    prep_fused<<<5120, 256>>>((const float4*)fc2, (__half2*)fc2h, fc1, fc1T);
    g1_kernel<<<dim3(8, 8, 4), 128, SMEM>>>(fc1T, fc2h, part,
                                            1024, 1024, 4096, 4096, 1024);
    fixup_k<<<dim3(32, 32), dim3(32, 8)>>>(part, bias, mask, attnT);

    // join, then GEMM2
    cudaStreamWaitEvent(0, evJoin, 0);
    hgemm2<<<dim3(8, 384), 256, SMEM>>>(xh, attnT, out, 49152, 1024, 1024);
    // NOTE: side/evFork/evJoin intentionally not destroyed — destroying
    // capture-referenced handles mid-capture is illegal; the handful of calls
    // the harness makes leaks a few KB of host-side handles, which is safe.
}

// round 16
// speedup vs baseline: 1.0614x; 1.0614x over previous
#include <cuda_runtime.h>
#include <cuda_fp16.h>
#include <cstdint>

// ============================================================================
// out = gelu( x @ ((fc1_w^T @ fc2_w^T + b) * mask) )   — fp32 in/out
// fp16 mma.sync.m16n8k16, f32 accumulate.
// R16: GEMM1 retiled to 64x64 (256 full-K CTAs) with a fused epilogue that
// applies bias+mask and writes attnT (f16, transposed) DIRECTLY — eliminating
// split-K partials (g_part) and the fixup kernel. cvt_x blocks stay fused in
// the same launch (R14-proven heterogeneous co-scheduling).
// GEMM2 = untouched R7/R14 kernel (proven 278us floor).
// ============================================================================

__device__ __half g_xh[49152 * 1024];
__device__ __half g_fc1T[1024 * 4096];
__device__ __half g_fc2h[1024 * 4096];
__device__ __half g_attnT[1024 * 1024];

// ---------------- helpers ---------------------------------------------------
__device__ __forceinline__ uint32_t smem_u32(const void* p) {
    uint32_t a;
    asm("{ .reg .u64 t; cvta.to.shared.u64 t, %1; cvt.u32.u64 %0, t; }" : "=r"(a) : "l"(p));
    return a;
}
#define CP_ASYNC16(sdst, gsrc) \
    asm volatile("cp.async.cg.shared.global [%0], [%1], 16;" :: "r"(sdst), "l"(gsrc) : "memory")
#define CP_COMMIT() asm volatile("cp.async.commit_group;" ::: "memory")
#define CP_WAIT1()  asm volatile("cp.async.wait_group 1;" ::: "memory")
#define CP_WAIT0()  asm volatile("cp.async.wait_group 0;" ::: "memory")
#define SWZ128(off) ((off) ^ (((off) >> 3) & 0x70))

__device__ __forceinline__ void ldsm_x4(uint32_t* r, uint32_t addr) {
    asm volatile("ldmatrix.sync.aligned.m8n8.x4.shared.b16 {%0,%1,%2,%3}, [%4];"
                 : "=r"(r[0]), "=r"(r[1]), "=r"(r[2]), "=r"(r[3]) : "r"(addr));
}
// fp16 MMA, fp32 accumulate: C[16x8] += A[16x16] * B[16x8]
__device__ __forceinline__ void mma_f16(float c[4], const uint32_t a[4], const uint32_t* b) {
    asm volatile(
        "mma.sync.aligned.m16n8k16.row.col.f32.f16.f16.f32 "
        "{%0,%1,%2,%3}, {%4,%5,%6,%7}, {%8,%9}, {%0,%1,%2,%3};"
        : "+f"(c[0]), "+f"(c[1]), "+f"(c[2]), "+f"(c[3])
        : "r"(a[0]), "r"(a[1]), "r"(a[2]), "r"(a[3]), "r"(b[0]), "r"(b[1]));
}
__device__ __forceinline__ float gelu_exact(float u) {
    return 0.5f * u * (1.0f + erff(u * 0.7071067811865476f));
}

constexpr int STAGES = 3;
constexpr int TBYTES  = 128 * 128;  // GEMM2 tile: 128 rows x 64 halfs (16KB)
constexpr int TB1     = 64 * 128;   // GEMM1 tile: 64 rows x 64 halfs (8KB)

// ---------------------------------------------------------------------------
// Fused GEMM1(64x64, direct attnT) + cvt_x.  128 threads/block, 48KB smem.
// Blocks [0,256): GEMM1 tile (by = b>>4 -> s band, bx = b&15 -> t band),
//   K=4096 full depth, 4 warps @ 32x32, epilogue writes
//   attnT[t][s] = half((acc + bias[t]) * mask[s][t]).
// Blocks [256, 2304): convert a slice of x to f16 (co-resident with GEMM1).
// ---------------------------------------------------------------------------
constexpr int G1_BLOCKS  = 256;
constexpr int CVT_BLOCKS = 2048;
constexpr int X_F4       = 49152 * 1024 / 4;          // 12,582,912
constexpr int F4_PER_CTA = X_F4 / CVT_BLOCKS;         // 6144 = 48 * 128

__global__ __launch_bounds__(128) void g1cvt_fused(
    const __half* __restrict__ A, const __half* __restrict__ B,
    const float* __restrict__ bias, const float* __restrict__ mask,
    __half* __restrict__ attnT,
    const float4* __restrict__ X, __half2* __restrict__ XH)
{
    extern __shared__ __align__(1024) char smem[];
    const int b = blockIdx.x;

    if (b >= G1_BLOCKS) {
        // ---- cvt_x slice: 48 coalesced float4 iterations per thread ----
        const int base = (b - G1_BLOCKS) * F4_PER_CTA + threadIdx.x;
#pragma unroll 8
        for (int k = 0; k < F4_PER_CTA / 128; k++) {
            const int i = base + k * 128;
            float4 v = X[i];
            XH[i * 2 + 0] = __floats2half2_rn(v.x, v.y);
            XH[i * 2 + 1] = __floats2half2_rn(v.z, v.w);
        }
        return;
    }

    // ---- GEMM1 64x64 tile, full K=4096 ----
    const uint32_t sb = smem_u32(smem);
    const int tid  = threadIdx.x;
    const int lane = tid & 31;
    const int wid  = tid >> 5;           // 0..3
    const int wm   = (wid & 1) * 32;
    const int wn   = (wid >> 1) * 32;
    const size_t bm = (size_t)(b >> 4) * 64;   // s band
    const size_t bn = (size_t)(b & 15) * 64;   // t band
    constexpr int K = 4096;
    constexpr int NK = K / 64;           // 64 chunks

    const int lr = tid >> 3;             // 0..15
    const int lc = tid & 7;
    auto issue = [&](int chunk) {
        const int buf = chunk % STAGES;
        const uint32_t aBase = sb + buf * TB1;
        const uint32_t bBase = sb + STAGES * TB1 + buf * TB1;
        const __half* ga = A + (bm + lr) * (size_t)K + chunk * 64 + lc * 8;
        const __half* gb = B + (bn + lr) * (size_t)K + chunk * 64 + lc * 8;
#pragma unroll
        for (int j = 0; j < 4; j++) {
            CP_ASYNC16(aBase + SWZ128((lr + j * 16) * 128 + lc * 16), ga + (size_t)(j * 16) * K);
            CP_ASYNC16(bBase + SWZ128((lr + j * 16) * 128 + lc * 16), gb + (size_t)(j * 16) * K);
        }
        CP_COMMIT();
    };

    float c[2][4][4];
#pragma unroll
    for (int im = 0; im < 2; im++)
#pragma unroll
        for (int in = 0; in < 4; in++)
#pragma unroll
            for (int q = 0; q < 4; q++) c[im][in][q] = 0.0f;

    issue(0);
    issue(1);

    const int aRow = lane & 15;
    const int aKo  = ((lane >> 4) & 1) * 16;
    const int bRow = (lane & 7) + ((lane >> 4) << 3);
    const int bKo  = ((lane >> 3) & 1) * 16;

    for (int i = 0; i < NK; i++) {
        if (i + 1 < NK) { CP_WAIT1(); } else { CP_WAIT0(); }
        __syncthreads();
        if (i + 2 < NK) issue(i + 2);

        const uint32_t aS = sb + (i % STAGES) * TB1;
        const uint32_t bS = sb + STAGES * TB1 + (i % STAGES) * TB1;
#pragma unroll
        for (int ks = 0; ks < 4; ks++) {
            uint32_t af[2][4];
#pragma unroll
            for (int im = 0; im < 2; im++)
                ldsm_x4(af[im], aS + SWZ128((wm + im * 16 + aRow) * 128 + ks * 32 + aKo));
#pragma unroll
            for (int nb = 0; nb < 2; nb++) {
                uint32_t bf[4];
                ldsm_x4(bf, bS + SWZ128((wn + nb * 16 + bRow) * 128 + ks * 32 + bKo));
#pragma unroll
                for (int im = 0; im < 2; im++) {
                    mma_f16(c[im][nb * 2 + 0], af[im], &bf[0]);
                    mma_f16(c[im][nb * 2 + 1], af[im], &bf[2]);
                }
            }
        }
    }

    // ---- epilogue: attnT[t][s] = half((acc + bias[t]) * mask[s][t]) ----
    const int g  = lane >> 2;
    const int tg = lane & 3;
#pragma unroll
    for (int im = 0; im < 2; im++) {
#pragma unroll
        for (int in = 0; in < 4; in++) {
            const size_t r0 = bm + wm + im * 16 + g;   // s
            const size_t r1 = r0 + 8;
            const size_t cc = bn + wn + in * 8 + tg * 2;  // t
            const float b0 = bias[cc], b1 = bias[cc + 1];
            attnT[cc * 1024 + r0] =
                __float2half_rn((c[im][in][0] + b0) * mask[r0 * 1024 + cc]);
            attnT[(cc + 1) * 1024 + r0] =
                __float2half_rn((c[im][in][1] + b1) * mask[r0 * 1024 + cc + 1]);
            attnT[cc * 1024 + r1] =
                __float2half_rn((c[im][in][2] + b0) * mask[r1 * 1024 + cc]);
            attnT[(cc + 1) * 1024 + r1] =
                __float2half_rn((c[im][in][3] + b1) * mask[r1 * 1024 + cc + 1]);
        }
    }
}

// ---------------------------------------------------------------------------
// GEMM2 (R7/R14 body, untouched): CTA 128x128, 256 thr, warp 32x64, 3-stage
// cp.async + wait_group(1), fragment double-buffering, gelu epilogue.
// ---------------------------------------------------------------------------
__global__ __launch_bounds__(256, 2) void hgemm2(
    const __half* __restrict__ A, const __half* __restrict__ B, float* __restrict__ C,
    int M, int N, int K)
{
    extern __shared__ __align__(1024) char smem[];
    const uint32_t sb = smem_u32(smem);
    const int tid  = threadIdx.x;
    const int lane = tid & 31;
    const int wid  = tid >> 5;
    const int wm   = (wid & 3) * 32;
    const int wn   = (wid >> 2) * 64;
    const size_t bm = (size_t)blockIdx.y * 128;
    const size_t bn = (size_t)blockIdx.x * 128;

    const int nk = K / 64;
    const int lr = tid >> 3;
    const int lc = tid & 7;
    auto issue = [&](int chunk) {
        const int buf = chunk % STAGES;
        const uint32_t aBase = sb + buf * TBYTES;
        const uint32_t bBase = sb + STAGES * TBYTES + buf * TBYTES;
        const __half* ga = A + (bm + lr) * (size_t)K + chunk * 64 + lc * 8;
        const __half* gb = B + (bn + lr) * (size_t)K + chunk * 64 + lc * 8;
#pragma unroll
        for (int j = 0; j < 4; j++) {
            CP_ASYNC16(aBase + SWZ128((lr + j * 32) * 128 + lc * 16), ga + (size_t)(j * 32) * K);
            CP_ASYNC16(bBase + SWZ128((lr + j * 32) * 128 + lc * 16), gb + (size_t)(j * 32) * K);
        }
        CP_COMMIT();
    };

    float c[2][8][4];
#pragma unroll
    for (int im = 0; im < 2; im++)
#pragma unroll
        for (int in = 0; in < 8; in++)
#pragma unroll
            for (int q = 0; q < 4; q++) c[im][in][q] = 0.0f;

    issue(0);
    issue(1);

    const int aRow = lane & 15;
    const int aKo  = ((lane >> 4) & 1) * 16;
    const int bRow = (lane & 7) + ((lane >> 4) << 3);
    const int bKo  = ((lane >> 3) & 1) * 16;

    auto loadA = [&](uint32_t (*f)[4], uint32_t aS, int ks) {
#pragma unroll
        for (int im = 0; im < 2; im++)
            ldsm_x4(f[im], aS + SWZ128((wm + im * 16 + aRow) * 128 + ks * 32 + aKo));
    };
    auto loadB = [&](uint32_t (*f)[4], uint32_t bS, int ks) {
#pragma unroll
        for (int nb = 0; nb < 4; nb++)
            ldsm_x4(f[nb], bS + SWZ128((wn + nb * 16 + bRow) * 128 + ks * 32 + bKo));
    };

    for (int i = 0; i < nk; i++) {
        if (i + 1 < nk) { CP_WAIT1(); } else { CP_WAIT0(); }
        __syncthreads();
        if (i + 2 < nk) issue(i + 2);

        const uint32_t aS = sb + (i % STAGES) * TBYTES;
        const uint32_t bS = sb + STAGES * TBYTES + (i % STAGES) * TBYTES;

        uint32_t af[2][2][4];
        uint32_t bf[2][4][4];
        loadA(af[0], aS, 0);
        loadB(bf[0], bS, 0);
#pragma unroll
        for (int ks = 0; ks < 4; ks++) {
            const int cur = ks & 1, nxt = cur ^ 1;
            if (ks < 3) {
                loadA(af[nxt], aS, ks + 1);
                loadB(bf[nxt], bS, ks + 1);
            }
#pragma unroll
            for (int im = 0; im < 2; im++)
#pragma unroll
                for (int nb = 0; nb < 4; nb++) {
                    mma_f16(c[im][nb * 2 + 0], af[cur][im], &bf[cur][nb][0]);
                    mma_f16(c[im][nb * 2 + 1], af[cur][im], &bf[cur][nb][2]);
                }
        }
    }

    const int g  = lane >> 2;
    const int tg = lane & 3;
#pragma unroll
    for (int im = 0; im < 2; im++) {
#pragma unroll
        for (int in = 0; in < 8; in++) {
            const size_t r0 = bm + wm + im * 16 + g;
            const size_t r1 = r0 + 8;
            const size_t cc = bn + wn + in * 8 + tg * 2;
            float v0 = gelu_exact(c[im][in][0]);
            float v1 = gelu_exact(c[im][in][1]);
            float v2 = gelu_exact(c[im][in][2]);
            float v3 = gelu_exact(c[im][in][3]);
            *reinterpret_cast<float2*>(C + r0 * N + cc) = make_float2(v0, v1);
            *reinterpret_cast<float2*>(C + r1 * N + cc) = make_float2(v2, v3);
        }
    }
}

// ---------------------------------------------------------------------------
// Fused prep: blocks [0,1024) = cvt_fc2, blocks [1024,5120) = transpose+cvt fc1.
// ---------------------------------------------------------------------------
__global__ __launch_bounds__(256) void prep_fused(
    const float4* __restrict__ fc2, __half2* __restrict__ fc2h,
    const float* __restrict__ fc1, __half* __restrict__ fc1T)
{
    const int b = blockIdx.x;
    if (b < 1024) {
        const int base = b * 1024 + threadIdx.x;
#pragma unroll
        for (int k = 0; k < 4; k++) {
            const int i = base + k * 256;
            float4 v = fc2[i];
            fc2h[i * 2 + 0] = __floats2half2_rn(v.x, v.y);
            fc2h[i * 2 + 1] = __floats2half2_rn(v.z, v.w);
        }
    } else {
        __shared__ float t[32][33];
        const int i  = b - 1024;
        const int bx = (i & 31) * 32;
        const int by = (i >> 5) * 32;
        const int x = threadIdx.x & 31;
        const int y = threadIdx.x >> 5;
#pragma unroll
        for (int j = 0; j < 32; j += 8)
            t[y + j][x] = fc1[(size_t)(by + y + j) * 1024 + bx + x];
        __syncthreads();
#pragma unroll
        for (int j = 0; j < 32; j += 8)
            fc1T[(size_t)(bx + y + j) * 4096 + by + x] = __float2half_rn(t[x][y + j]);
    }
}

// ---------------------------------------------------------------------------
extern "C" void kernel_launch(void* const* d_in, const int* in_sizes, int n_in,
                              void* d_out, int out_size)
{
    const float* x    = (const float*)d_in[0];
    const float* fc1  = (const float*)d_in[1];
    const float* fc2  = (const float*)d_in[2];
    const float* bias = (const float*)d_in[3];
    const float* mask = (const float*)d_in[4];
    float* out = (float*)d_out;

    __half *xh, *fc1T, *fc2h, *attnT;
    cudaGetSymbolAddress((void**)&xh, g_xh);
    cudaGetSymbolAddress((void**)&fc1T, g_fc1T);
    cudaGetSymbolAddress((void**)&fc2h, g_fc2h);
    cudaGetSymbolAddress((void**)&attnT, g_attnT);

    constexpr int SMEM1 = 2 * STAGES * TB1;     // 49152
    constexpr int SMEM2 = 2 * STAGES * TBYTES;  // 98304
    cudaFuncSetAttribute(g1cvt_fused, cudaFuncAttributeMaxDynamicSharedMemorySize, SMEM1);
    cudaFuncSetAttribute(hgemm2, cudaFuncAttributeMaxDynamicSharedMemorySize, SMEM2);

    // 1. fused prep: fc2 -> f16, fc1 -> transposed f16
    prep_fused<<<5120, 256>>>((const float4*)fc2, (__half2*)fc2h, fc1, fc1T);

    // 2. fused GEMM1 (64x64, full-K, direct attnT epilogue) + cvt_x
    g1cvt_fused<<<G1_BLOCKS + CVT_BLOCKS, 128, SMEM1>>>(
        fc1T, fc2h, bias, mask, attnT, (const float4*)x, (__half2*)xh);

    // 3. GEMM2: out = gelu(xh · attnT^T)
    hgemm2<<<dim3(8, 384), 256, SMEM2>>>(xh, attnT, out, 49152, 1024, 1024);
}